// round 1
// baseline (speedup 1.0000x reference)
#include <cuda_runtime.h>

// FSQ: x (64, 32768, 4) fp32.
// N = 64*32768 = 2097152 tokens, D=4 channels, LEVELS = [8,5,5,5].
// Outputs (concatenated in d_out, fp32):
//   z: stacked as (D, N) then reshaped -> out[d*N + n] = quantized tanh(x[n,d])
//   code: out[4*N + n] = (float)(i0 + 8*i1 + 40*i2 + 200*i3)

#define FSQ_N (64 * 32768)

__global__ __launch_bounds__(256) void fsq_kernel(const float4* __restrict__ x4,
                                                  float* __restrict__ out) {
    int n = blockIdx.x * blockDim.x + threadIdx.x;
    if (n >= FSQ_N) return;

    float4 v = x4[n];

    // channel 0: 8 levels
    float t0 = tanhf(v.x);
    int i0 = __float2int_rn((t0 + 1.0f) * 3.5f);        // (8-1)/2
    float q0 = (float)i0 * (2.0f / 7.0f) - 1.0f;

    // channel 1: 5 levels
    float t1 = tanhf(v.y);
    int i1 = __float2int_rn((t1 + 1.0f) * 2.0f);        // (5-1)/2
    float q1 = (float)i1 * 0.5f - 1.0f;

    // channel 2: 5 levels
    float t2 = tanhf(v.z);
    int i2 = __float2int_rn((t2 + 1.0f) * 2.0f);
    float q2 = (float)i2 * 0.5f - 1.0f;

    // channel 3: 5 levels
    float t3 = tanhf(v.w);
    int i3 = __float2int_rn((t3 + 1.0f) * 2.0f);
    float q3 = (float)i3 * 0.5f - 1.0f;

    out[0 * FSQ_N + n] = q0;
    out[1 * FSQ_N + n] = q1;
    out[2 * FSQ_N + n] = q2;
    out[3 * FSQ_N + n] = q3;

    int code = i0 + 8 * i1 + 40 * i2 + 200 * i3;
    out[4 * FSQ_N + n] = (float)code;
}

extern "C" void kernel_launch(void* const* d_in, const int* in_sizes, int n_in,
                              void* d_out, int out_size) {
    const float4* x4 = (const float4*)d_in[0];
    float* out = (float*)d_out;
    const int threads = 256;
    const int blocks = (FSQ_N + threads - 1) / threads;  // 8192
    fsq_kernel<<<blocks, threads>>>(x4, out);
}

// round 2
// speedup vs baseline: 1.0175x; 1.0175x over previous
#include <cuda_runtime.h>

// FSQ: x (64, 32768, 4) fp32. N = 2097152 tokens, LEVELS = [8,5,5,5].
// out fp32: z planes out[d*N + n] = level_d(idx_d), code plane out[4*N + n].
// Fast quantizer: (tanh(x)+1) = 2/(1+e^(-2x)) = 2*rcp(1+ex2(-2x*log2e)),
// idx = rint(rcp(1+ex2(-2x*log2e)) * (n_levels-1)).

#define FSQ_N (64 * 32768)
#define NTOK_PER_THREAD 4

__device__ __forceinline__ float fast_ex2(float x) {
    float y;
    asm("ex2.approx.f32 %0, %1;" : "=f"(y) : "f"(x));
    return y;
}
__device__ __forceinline__ float fast_rcp(float x) {
    float y;
    asm("rcp.approx.f32 %0, %1;" : "=f"(y) : "f"(x));
    return y;
}

// returns idx, writes q
__device__ __forceinline__ int quant(float x, float two_s, float step, float& q) {
    const float NEG2LOG2E = -2.8853900817779268f;  // -2*log2(e)
    float t = x * NEG2LOG2E;
    float e = fast_ex2(t);              // e^(-2x)
    float r = fast_rcp(1.0f + e);       // (tanh(x)+1)/2
    int idx = __float2int_rn(r * two_s);
    q = (float)idx * step - 1.0f;
    return idx;
}

__global__ __launch_bounds__(256) void fsq_kernel(const float4* __restrict__ x4,
                                                  float4* __restrict__ out4) {
    int tid = blockIdx.x * blockDim.x + threadIdx.x;   // one thread = 4 tokens
    if (tid >= FSQ_N / NTOK_PER_THREAD) return;

    float4 z0, z1, z2, z3, zc;   // plane-major outputs for tokens 4t..4t+3

    float4 v;
    float q;
    int i0, i1, i2, i3;

    // token 4t+0
    v = x4[4 * tid + 0];
    i0 = quant(v.x, 7.0f, 2.0f / 7.0f, q); z0.x = q;
    i1 = quant(v.y, 4.0f, 0.5f, q);        z1.x = q;
    i2 = quant(v.z, 4.0f, 0.5f, q);        z2.x = q;
    i3 = quant(v.w, 4.0f, 0.5f, q);        z3.x = q;
    zc.x = (float)(i0 + 8 * i1 + 40 * i2 + 200 * i3);

    // token 4t+1
    v = x4[4 * tid + 1];
    i0 = quant(v.x, 7.0f, 2.0f / 7.0f, q); z0.y = q;
    i1 = quant(v.y, 4.0f, 0.5f, q);        z1.y = q;
    i2 = quant(v.z, 4.0f, 0.5f, q);        z2.y = q;
    i3 = quant(v.w, 4.0f, 0.5f, q);        z3.y = q;
    zc.y = (float)(i0 + 8 * i1 + 40 * i2 + 200 * i3);

    // token 4t+2
    v = x4[4 * tid + 2];
    i0 = quant(v.x, 7.0f, 2.0f / 7.0f, q); z0.z = q;
    i1 = quant(v.y, 4.0f, 0.5f, q);        z1.z = q;
    i2 = quant(v.z, 4.0f, 0.5f, q);        z2.z = q;
    i3 = quant(v.w, 4.0f, 0.5f, q);        z3.z = q;
    zc.z = (float)(i0 + 8 * i1 + 40 * i2 + 200 * i3);

    // token 4t+3
    v = x4[4 * tid + 3];
    i0 = quant(v.x, 7.0f, 2.0f / 7.0f, q); z0.w = q;
    i1 = quant(v.y, 4.0f, 0.5f, q);        z1.w = q;
    i2 = quant(v.z, 4.0f, 0.5f, q);        z2.w = q;
    i3 = quant(v.w, 4.0f, 0.5f, q);        z3.w = q;
    zc.w = (float)(i0 + 8 * i1 + 40 * i2 + 200 * i3);

    const int PN4 = FSQ_N / 4;   // plane size in float4 units
    out4[0 * PN4 + tid] = z0;
    out4[1 * PN4 + tid] = z1;
    out4[2 * PN4 + tid] = z2;
    out4[3 * PN4 + tid] = z3;
    out4[4 * PN4 + tid] = zc;
}

extern "C" void kernel_launch(void* const* d_in, const int* in_sizes, int n_in,
                              void* d_out, int out_size) {
    const float4* x4 = (const float4*)d_in[0];
    float4* out4 = (float4*)d_out;
    const int threads = 256;
    const int total_threads = FSQ_N / NTOK_PER_THREAD;   // 524288
    const int blocks = total_threads / threads;          // 2048
    fsq_kernel<<<blocks, threads>>>(x4, out4);
}